// round 9
// baseline (speedup 1.0000x reference)
#include <cuda_runtime.h>
#include <cuda_bf16.h>
#include <math.h>

#define N_NODES  50000
#define N_EDGES  1600000
#define EG       (N_EDGES / 4)
#define IN_CH    64
#define HID      16
#define NCLS     10
#define HID2P    12

// ---------------- device scratch ----------------
__device__ __align__(16) float g_y1  [N_NODES * HID];    // x @ w_rel1
__device__ __align__(16) float g_r1  [N_NODES * HID];    // x @ w_root1
__device__ __align__(16) float g_agg1[N_NODES * HID];    // segment_sum(y1)
__device__ __align__(16) float g_y2  [N_NODES * HID2P];  // h @ w_rel2 (padded)
__device__ __align__(16) float g_r2  [N_NODES * HID2P];  // h @ w_root2
__device__ __align__(16) float g_agg2[N_NODES * HID2P];  // segment_sum(y2)
__device__ int g_is64;                                   // edge dtype flag

// ---------------- kernels ----------------

// y1 = x @ w_rel1, zero agg1, detect edge dtype (last block).
__global__ __launch_bounds__(256) void k_lin1y(const float* __restrict__ x,
                                               const float* __restrict__ w_rel,
                                               const int* __restrict__ ei32) {
    if (blockIdx.x == gridDim.x - 1) {
        __shared__ int s_or;
        if (threadIdx.x == 0) s_or = 0;
        __syncthreads();
        int v = 0;
        for (int i = threadIdx.x; i < 1024; i += 256)
            v |= ei32[2 * i + 1];
        if (v) atomicOr(&s_or, 1);
        __syncthreads();
        if (threadIdx.x == 0) g_is64 = (s_or == 0) ? 1 : 0;
        return;
    }

    __shared__ float sw[IN_CH * HID];
    for (int i = threadIdx.x; i < IN_CH * HID; i += 256) sw[i] = w_rel[i];
    __syncthreads();

    int t = blockIdx.x * 256 + threadIdx.x;
    int pair = t >> 2;
    if (pair >= N_NODES / 2) return;
    int part = t & 3;
    int jbase = part * 4;
    int n0 = pair * 2, n1 = n0 + 1;

    {
        float4 z = make_float4(0.f, 0.f, 0.f, 0.f);
        float4* az = reinterpret_cast<float4*>(g_agg1 + (size_t)pair * 2 * HID);
        az[2 * part] = z;
        az[2 * part + 1] = z;
    }

    float a0[4] = {0.f, 0.f, 0.f, 0.f};
    float a1[4] = {0.f, 0.f, 0.f, 0.f};
    const float4* x0 = reinterpret_cast<const float4*>(x + (size_t)n0 * IN_CH);
    const float4* x1 = reinterpret_cast<const float4*>(x + (size_t)n1 * IN_CH);
#pragma unroll
    for (int k4 = 0; k4 < IN_CH / 4; k4++) {
        float4 v0 = __ldg(x0 + k4);
        float4 v1 = __ldg(x1 + k4);
        float s0[4] = {v0.x, v0.y, v0.z, v0.w};
        float s1[4] = {v1.x, v1.y, v1.z, v1.w};
#pragma unroll
        for (int u = 0; u < 4; u++) {
            const float* wr = sw + (k4 * 4 + u) * HID + jbase;
#pragma unroll
            for (int j = 0; j < 4; j++) {
                float wv = wr[j];
                a0[j] = fmaf(s0[u], wv, a0[j]);
                a1[j] = fmaf(s1[u], wv, a1[j]);
            }
        }
    }
    *reinterpret_cast<float4*>(g_y1 + (size_t)n0 * HID + jbase) =
        make_float4(a0[0], a0[1], a0[2], a0[3]);
    *reinterpret_cast<float4*>(g_y1 + (size_t)n1 * HID + jbase) =
        make_float4(a1[0], a1[1], a1[2], a1[3]);
}

// r1 = x @ w_root1, zero agg2 (side stream).
__global__ __launch_bounds__(256) void k_lin1r(const float* __restrict__ x,
                                               const float* __restrict__ w_root) {
    __shared__ float su[IN_CH * HID];
    for (int i = threadIdx.x; i < IN_CH * HID; i += 256) su[i] = w_root[i];
    __syncthreads();

    int t = blockIdx.x * 256 + threadIdx.x;
    int pair = t >> 2;
    if (pair >= N_NODES / 2) return;
    int part = t & 3;
    int jbase = part * 4;
    int n0 = pair * 2, n1 = n0 + 1;

    {
        float4 z = make_float4(0.f, 0.f, 0.f, 0.f);
        float4* az = reinterpret_cast<float4*>(g_agg2 + (size_t)pair * 2 * HID2P);
        if (part == 0)      { az[0] = z; az[1] = z; }
        else if (part == 1) { az[2] = z; az[3] = z; }
        else if (part == 2) { az[4] = z; }
        else                { az[5] = z; }
    }

    float a0[4] = {0.f, 0.f, 0.f, 0.f};
    float a1[4] = {0.f, 0.f, 0.f, 0.f};
    const float4* x0 = reinterpret_cast<const float4*>(x + (size_t)n0 * IN_CH);
    const float4* x1 = reinterpret_cast<const float4*>(x + (size_t)n1 * IN_CH);
#pragma unroll
    for (int k4 = 0; k4 < IN_CH / 4; k4++) {
        float4 v0 = __ldg(x0 + k4);
        float4 v1 = __ldg(x1 + k4);
        float s0[4] = {v0.x, v0.y, v0.z, v0.w};
        float s1[4] = {v1.x, v1.y, v1.z, v1.w};
#pragma unroll
        for (int u = 0; u < 4; u++) {
            const float* wr = su + (k4 * 4 + u) * HID + jbase;
#pragma unroll
            for (int j = 0; j < 4; j++) {
                float wv = wr[j];
                a0[j] = fmaf(s0[u], wv, a0[j]);
                a1[j] = fmaf(s1[u], wv, a1[j]);
            }
        }
    }
    *reinterpret_cast<float4*>(g_r1 + (size_t)n0 * HID + jbase) =
        make_float4(a0[0], a0[1], a0[2], a0[3]);
    *reinterpret_cast<float4*>(g_r1 + (size_t)n1 * HID + jbase) =
        make_float4(a1[0], a1[1], a1[2], a1[3]);
}

// Layer-1 scatter, ILP=4: lanes q=0..3 share an edge group (coalesced rows).
__global__ __launch_bounds__(256) void k_scat1(const void* __restrict__ ei) {
    const bool is64 = (g_is64 != 0);
    int t = blockIdx.x * 256 + threadIdx.x;
    int eg = t >> 2;
    if (eg >= EG) return;
    int q = t & 3;
    int s[4], d[4];
    if (is64) {
        const long long* p = (const long long*)ei;
#pragma unroll
        for (int i = 0; i < 4; i++) {
            s[i] = (int)p[eg * 4 + i];
            d[i] = (int)p[N_EDGES + eg * 4 + i];
        }
    } else {
        const int* p = (const int*)ei;
        int4 sv = __ldg(reinterpret_cast<const int4*>(p) + eg);
        int4 dv = __ldg(reinterpret_cast<const int4*>(p + N_EDGES) + eg);
        s[0] = sv.x; s[1] = sv.y; s[2] = sv.z; s[3] = sv.w;
        d[0] = dv.x; d[1] = dv.y; d[2] = dv.z; d[3] = dv.w;
    }
    float4 v[4];
#pragma unroll
    for (int i = 0; i < 4; i++)
        v[i] = __ldg(reinterpret_cast<const float4*>(g_y1 + (size_t)s[i] * HID) + q);
#pragma unroll
    for (int i = 0; i < 4; i++) {
        float* dp = g_agg1 + (size_t)d[i] * HID + q * 4;
        asm volatile("red.global.add.v4.f32 [%0], {%1, %2, %3, %4};"
                     :: "l"(dp), "f"(v[i].x), "f"(v[i].y), "f"(v[i].z), "f"(v[i].w)
                     : "memory");
    }
}

// y2 = relu(agg1+b1+r1) @ w_rel2 (padded to 12).
// 4 threads per node; each loads its own float4 of agg1/r1 (no redundancy),
// computes partial 10-class dot, shfl_xor-reduces within the 4-lane group.
__global__ __launch_bounds__(256) void k_lin2h(const float* __restrict__ b1,
                                               const float* __restrict__ w_rel2) {
    __shared__ float sw[HID * NCLS];
    __shared__ float sb[HID];
    for (int i = threadIdx.x; i < HID * NCLS; i += 256) sw[i] = w_rel2[i];
    if (threadIdx.x < HID) sb[threadIdx.x] = b1[threadIdx.x];
    __syncthreads();

    int t = blockIdx.x * 256 + threadIdx.x;
    int node = t >> 2;
    int sub = t & 3;
    bool valid = (node < N_NODES);

    float h[4] = {0.f, 0.f, 0.f, 0.f};
    if (valid) {
        float4 a = *(reinterpret_cast<const float4*>(g_agg1 + (size_t)node * HID) + sub);
        float4 r = *(reinterpret_cast<const float4*>(g_r1 + (size_t)node * HID) + sub);
        float v0 = a.x + sb[sub*4+0] + r.x;
        float v1 = a.y + sb[sub*4+1] + r.y;
        float v2 = a.z + sb[sub*4+2] + r.z;
        float v3 = a.w + sb[sub*4+3] + r.w;
        h[0] = v0 > 0.f ? v0 : 0.f;
        h[1] = v1 > 0.f ? v1 : 0.f;
        h[2] = v2 > 0.f ? v2 : 0.f;
        h[3] = v3 > 0.f ? v3 : 0.f;
    }
    float y[NCLS];
#pragma unroll
    for (int c = 0; c < NCLS; c++) y[c] = 0.f;
#pragma unroll
    for (int j = 0; j < 4; j++) {
        const float* wr = sw + (sub * 4 + j) * NCLS;
#pragma unroll
        for (int c = 0; c < NCLS; c++)
            y[c] = fmaf(h[j], wr[c], y[c]);
    }
#pragma unroll
    for (int c = 0; c < NCLS; c++) {
        y[c] += __shfl_xor_sync(0xffffffff, y[c], 1);
        y[c] += __shfl_xor_sync(0xffffffff, y[c], 2);
    }
    if (valid && sub == 0) {
        float4* y2 = reinterpret_cast<float4*>(g_y2 + (size_t)node * HID2P);
        y2[0] = make_float4(y[0], y[1], y[2], y[3]);
        y2[1] = make_float4(y[4], y[5], y[6], y[7]);
        y2[2] = make_float4(y[8], y[9], 0.f, 0.f);
    }
}

// r2 = relu(agg1+b1+r1) @ w_root2 — recomputes h itself; runs on the side
// stream concurrently with k_lin2h (both only depend on scat1 + lin1r).
__global__ __launch_bounds__(256) void k_lin2r(const float* __restrict__ b1,
                                               const float* __restrict__ w_root2) {
    __shared__ float su[HID * NCLS];
    __shared__ float sb[HID];
    for (int i = threadIdx.x; i < HID * NCLS; i += 256) su[i] = w_root2[i];
    if (threadIdx.x < HID) sb[threadIdx.x] = b1[threadIdx.x];
    __syncthreads();

    int t = blockIdx.x * 256 + threadIdx.x;
    int node = t >> 2;
    int sub = t & 3;
    bool valid = (node < N_NODES);

    float h[4] = {0.f, 0.f, 0.f, 0.f};
    if (valid) {
        float4 a = *(reinterpret_cast<const float4*>(g_agg1 + (size_t)node * HID) + sub);
        float4 r = *(reinterpret_cast<const float4*>(g_r1 + (size_t)node * HID) + sub);
        float v0 = a.x + sb[sub*4+0] + r.x;
        float v1 = a.y + sb[sub*4+1] + r.y;
        float v2 = a.z + sb[sub*4+2] + r.z;
        float v3 = a.w + sb[sub*4+3] + r.w;
        h[0] = v0 > 0.f ? v0 : 0.f;
        h[1] = v1 > 0.f ? v1 : 0.f;
        h[2] = v2 > 0.f ? v2 : 0.f;
        h[3] = v3 > 0.f ? v3 : 0.f;
    }
    float y[NCLS];
#pragma unroll
    for (int c = 0; c < NCLS; c++) y[c] = 0.f;
#pragma unroll
    for (int j = 0; j < 4; j++) {
        const float* wr = su + (sub * 4 + j) * NCLS;
#pragma unroll
        for (int c = 0; c < NCLS; c++)
            y[c] = fmaf(h[j], wr[c], y[c]);
    }
#pragma unroll
    for (int c = 0; c < NCLS; c++) {
        y[c] += __shfl_xor_sync(0xffffffff, y[c], 1);
        y[c] += __shfl_xor_sync(0xffffffff, y[c], 2);
    }
    if (valid && sub == 0) {
        float4* r2 = reinterpret_cast<float4*>(g_r2 + (size_t)node * HID2P);
        r2[0] = make_float4(y[0], y[1], y[2], y[3]);
        r2[1] = make_float4(y[4], y[5], y[6], y[7]);
        r2[2] = make_float4(y[8], y[9], 0.f, 0.f);
    }
}

// Layer-2 scatter, ILP=4.
__global__ __launch_bounds__(256) void k_scat2(const void* __restrict__ ei) {
    const bool is64 = (g_is64 != 0);
    unsigned t = blockIdx.x * 256 + threadIdx.x;
    if (t >= 3u * EG) return;
    unsigned eg = (unsigned)(((unsigned long long)t * 0x55555556ULL) >> 32);  // t/3
    unsigned q = t - eg * 3u;
    int s[4], d[4];
    if (is64) {
        const long long* p = (const long long*)ei;
#pragma unroll
        for (int i = 0; i < 4; i++) {
            s[i] = (int)p[eg * 4 + i];
            d[i] = (int)p[N_EDGES + eg * 4 + i];
        }
    } else {
        const int* p = (const int*)ei;
        int4 sv = __ldg(reinterpret_cast<const int4*>(p) + eg);
        int4 dv = __ldg(reinterpret_cast<const int4*>(p + N_EDGES) + eg);
        s[0] = sv.x; s[1] = sv.y; s[2] = sv.z; s[3] = sv.w;
        d[0] = dv.x; d[1] = dv.y; d[2] = dv.z; d[3] = dv.w;
    }
    float4 v[4];
#pragma unroll
    for (int i = 0; i < 4; i++)
        v[i] = __ldg(reinterpret_cast<const float4*>(g_y2 + (size_t)s[i] * HID2P) + q);
#pragma unroll
    for (int i = 0; i < 4; i++) {
        float* dp = g_agg2 + (size_t)d[i] * HID2P + q * 4;
        asm volatile("red.global.add.v4.f32 [%0], {%1, %2, %3, %4};"
                     :: "l"(dp), "f"(v[i].x), "f"(v[i].y), "f"(v[i].z), "f"(v[i].w)
                     : "memory");
    }
}

// out = log_softmax(agg2 + b2 + r2)
__global__ __launch_bounds__(128) void k_out(const float* __restrict__ b2,
                                             float* __restrict__ out) {
    __shared__ float sb[NCLS];
    if (threadIdx.x < NCLS) sb[threadIdx.x] = b2[threadIdx.x];
    __syncthreads();

    int node = blockIdx.x * 128 + threadIdx.x;
    if (node >= N_NODES) return;

    float o[NCLS];
#pragma unroll
    for (int c = 0; c < NCLS; c++)
        o[c] = g_agg2[(size_t)node * HID2P + c] + sb[c] + g_r2[(size_t)node * HID2P + c];

    float m = o[0];
#pragma unroll
    for (int c = 1; c < NCLS; c++) m = fmaxf(m, o[c]);
    float sum = 0.f;
#pragma unroll
    for (int c = 0; c < NCLS; c++) sum += __expf(o[c] - m);
    float ls = m + logf(sum);
#pragma unroll
    for (int c = 0; c < NCLS; c++)
        out[(size_t)node * NCLS + c] = o[c] - ls;
}

// ---------------- launch ----------------
extern "C" void kernel_launch(void* const* d_in, const int* in_sizes, int n_in,
                              void* d_out, int out_size) {
    const float* x       = (const float*)d_in[0];
    const void*  ei      = d_in[1];
    const float* w_rel1  = (const float*)d_in[2];
    const float* b_rel1  = (const float*)d_in[3];
    const float* w_root1 = (const float*)d_in[4];
    const float* w_rel2  = (const float*)d_in[5];
    const float* b_rel2  = (const float*)d_in[6];
    const float* w_root2 = (const float*)d_in[7];
    float* out = (float*)d_out;

    static cudaStream_t s2 = nullptr;
    static cudaEvent_t ev0, evR1, evS1, evR2;
    if (!s2) {
        cudaStreamCreateWithFlags(&s2, cudaStreamNonBlocking);
        cudaEventCreateWithFlags(&ev0,  cudaEventDisableTiming);
        cudaEventCreateWithFlags(&evR1, cudaEventDisableTiming);
        cudaEventCreateWithFlags(&evS1, cudaEventDisableTiming);
        cudaEventCreateWithFlags(&evR2, cudaEventDisableTiming);
    }

    const int lin1Blocks = (N_NODES / 2 * 4 + 255) / 256;      // 391
    const int lin2Blocks = (N_NODES * 4 + 255) / 256;          // 782
    const int nodeBlocks = (N_NODES + 127) / 128;
    const int scat1Blocks = (EG * 4 + 255) / 256;
    const int scat2Blocks = ((int)(3u * EG) + 255) / 256;

    cudaEventRecord(ev0, 0);
    cudaStreamWaitEvent(s2, ev0, 0);

    k_lin1y<<<lin1Blocks + 1, 256>>>(x, w_rel1, (const int*)ei);   // +1 detect
    k_lin1r<<<lin1Blocks, 256, 0, s2>>>(x, w_root1);
    cudaEventRecord(evR1, s2);

    k_scat1<<<scat1Blocks, 256>>>(ei);
    cudaEventRecord(evS1, 0);

    // lin2h on main (needs r1 + agg1); lin2r concurrently on side stream.
    cudaStreamWaitEvent(0, evR1, 0);
    cudaStreamWaitEvent(s2, evS1, 0);
    k_lin2h<<<lin2Blocks, 256>>>(b_rel1, w_rel2);
    k_lin2r<<<lin2Blocks, 256, 0, s2>>>(b_rel1, w_root2);
    cudaEventRecord(evR2, s2);

    k_scat2<<<scat2Blocks, 256>>>(ei);

    cudaStreamWaitEvent(0, evR2, 0);
    k_out<<<nodeBlocks, 128>>>(b_rel2, out);
}